// round 1
// baseline (speedup 1.0000x reference)
#include <cuda_runtime.h>
#include <cstddef>

#define AGENTS 8192
#define FDIM   128
#define PDIM   16
#define EDGES  262144

// Scratch: packed per-row vectors.
// g_p[i] = [ alpha_i * nf_i (128) | (gamma_i/F) * diff_i (128) ]   (src side)
// g_q[i] = [ nf_i (128)           | diff_i (128) ]                 (dst side)
__device__ float g_p[(size_t)AGENTS * 2 * FDIM];
__device__ float g_q[(size_t)AGENTS * 2 * FDIM];
__device__ float g_beta[AGENTS];

// ---------------------------------------------------------------------------
// Kernel 1: per-row prep. One 128-thread block per row.
// diff = feature - next_feature
// nf   = double L2-normalized next_feature (matches reference exactly)
// persona-weighted scalars a,b,g per row.
// ---------------------------------------------------------------------------
__global__ void __launch_bounds__(128) prep_kernel(
    const float* __restrict__ feature,
    const float* __restrict__ next_feature,
    const float* __restrict__ persona,
    const float* __restrict__ alpha,
    const float* __restrict__ beta,
    const float* __restrict__ gamma)
{
    const int row = blockIdx.x;
    const int tid = threadIdx.x;  // 0..127

    // persona-weighted scalars (redundant per thread; all L1 hits)
    float a = 0.f, b = 0.f, g = 0.f;
#pragma unroll
    for (int k = 0; k < PDIM; k++) {
        float pv = persona[row * PDIM + k];
        a = fmaf(pv, alpha[k], a);
        b = fmaf(pv, beta[k],  b);
        g = fmaf(pv, gamma[k], g);
    }

    const float f   = feature[(size_t)row * FDIM + tid];
    const float nf0 = next_feature[(size_t)row * FDIM + tid];
    const float diff = f - nf0;

    __shared__ float red[4];

    // first normalize
    float s = nf0 * nf0;
#pragma unroll
    for (int o = 16; o > 0; o >>= 1) s += __shfl_xor_sync(0xffffffffu, s, o);
    if ((tid & 31) == 0) red[tid >> 5] = s;
    __syncthreads();
    float n1 = sqrtf(red[0] + red[1] + red[2] + red[3]);
    float nf1 = nf0 / n1;
    __syncthreads();

    // second normalize (reference normalizes twice)
    s = nf1 * nf1;
#pragma unroll
    for (int o = 16; o > 0; o >>= 1) s += __shfl_xor_sync(0xffffffffu, s, o);
    if ((tid & 31) == 0) red[tid >> 5] = s;
    __syncthreads();
    float n2 = sqrtf(red[0] + red[1] + red[2] + red[3]);
    float nf = nf1 / n2;

    const size_t base = (size_t)row * 2 * FDIM;
    g_q[base + tid]        = nf;
    g_q[base + FDIM + tid] = diff;
    g_p[base + tid]        = a * nf;
    g_p[base + FDIM + tid] = (g * (1.0f / (float)FDIM)) * diff;
    if (tid == 0) g_beta[row] = b;
}

// ---------------------------------------------------------------------------
// Kernel 2: zero the 256MB output with 128-bit stores.
// ---------------------------------------------------------------------------
__global__ void __launch_bounds__(256) zero_kernel(float4* __restrict__ out)
{
    size_t i = (size_t)blockIdx.x * blockDim.x + threadIdx.x;
    out[i] = make_float4(0.f, 0.f, 0.f, 0.f);
}

// ---------------------------------------------------------------------------
// Kernel 3: act edges — one warp per edge, 256-dim dot = sim + impact fused.
// value = dot(p[src], q[dst]); atomicAdd into out[src, dst].
// ---------------------------------------------------------------------------
__global__ void __launch_bounds__(256) act_kernel(
    const int* __restrict__ src,
    const int* __restrict__ dst,
    float* __restrict__ out)
{
    const int widx = (int)(((size_t)blockIdx.x * blockDim.x + threadIdx.x) >> 5);
    const int lane = threadIdx.x & 31;
    if (widx >= EDGES) return;

    const int s = src[widx];
    const int d = dst[widx];

    const float4* __restrict__ pp = (const float4*)(g_p + (size_t)s * 2 * FDIM);
    const float4* __restrict__ qq = (const float4*)(g_q + (size_t)d * 2 * FDIM);

    // 256 floats = 64 float4; each lane takes 2 float4 from each array
    float4 p0 = pp[lane];
    float4 p1 = pp[lane + 32];
    float4 q0 = qq[lane];
    float4 q1 = qq[lane + 32];

    float acc = p0.x * q0.x;
    acc = fmaf(p0.y, q0.y, acc);
    acc = fmaf(p0.z, q0.z, acc);
    acc = fmaf(p0.w, q0.w, acc);
    acc = fmaf(p1.x, q1.x, acc);
    acc = fmaf(p1.y, q1.y, acc);
    acc = fmaf(p1.z, q1.z, acc);
    acc = fmaf(p1.w, q1.w, acc);

#pragma unroll
    for (int o = 16; o > 0; o >>= 1) acc += __shfl_xor_sync(0xffffffffu, acc, o);

    if (lane == 0) atomicAdd(&out[(size_t)s * AGENTS + d], acc);
}

// ---------------------------------------------------------------------------
// Kernel 4: cost edges — one thread per edge, subtract beta_row[src].
// ---------------------------------------------------------------------------
__global__ void __launch_bounds__(256) cost_kernel(
    const int* __restrict__ src,
    const int* __restrict__ dst,
    float* __restrict__ out)
{
    const int e = (int)((size_t)blockIdx.x * blockDim.x + threadIdx.x);
    if (e >= EDGES) return;
    const int s = src[e];
    const int d = dst[e];
    atomicAdd(&out[(size_t)s * AGENTS + d], -g_beta[s]);
}

// ---------------------------------------------------------------------------
extern "C" void kernel_launch(void* const* d_in, const int* in_sizes, int n_in,
                              void* d_out, int out_size)
{
    const float* feature      = (const float*)d_in[0];
    const float* next_feature = (const float*)d_in[1];
    const float* persona_t    = (const float*)d_in[2];
    const float* alpha        = (const float*)d_in[3];
    const float* beta         = (const float*)d_in[4];
    const float* gamma        = (const float*)d_in[5];
    const int*   act_src      = (const int*)d_in[6];
    const int*   act_dst      = (const int*)d_in[7];
    const int*   edge_src     = (const int*)d_in[8];
    const int*   edge_dst     = (const int*)d_in[9];
    float* out = (float*)d_out;

    // 1) per-row prep (independent of zeroing)
    prep_kernel<<<AGENTS, 128>>>(feature, next_feature, persona_t,
                                 alpha, beta, gamma);

    // 2) zero the output: 64M floats = 16M float4 -> 65536 blocks x 256
    const size_t n_f4 = (size_t)AGENTS * AGENTS / 4;
    zero_kernel<<<(unsigned)(n_f4 / 256), 256>>>((float4*)out);

    // 3) act edges: one warp per edge, 8 warps per block
    act_kernel<<<EDGES / 8, 256>>>(act_src, act_dst, out);

    // 4) cost edges: one thread per edge
    cost_kernel<<<EDGES / 256, 256>>>(edge_src, edge_dst, out);
}